// round 1
// baseline (speedup 1.0000x reference)
#include <cuda_runtime.h>
#include <math.h>

#define SEQ 8192
#define DM  2048
#define DK  128

// Scratch for projected Q/K/V (device globals: no allocation allowed)
__device__ float g_Q[SEQ * DK];
__device__ float g_K[SEQ * DK];
__device__ float g_V[SEQ * DK];

// ---------------------------------------------------------------------------
// Kernel 1: fused QKV projection.  out = x @ W^T + b
//   x: [SEQ, DM] row-major, W: [DK, DM] row-major, b: [DK]
// Tiling: BM=128 rows of x, BN=128 (=DK, all output cols), BK=16.
// 256 threads, each computes an 8x8 micro-tile.
// Shared strides padded to 130 floats -> the 4-way STS scatter of each float4
// hits 32 distinct banks (4*130 % 32 = 8; offsets {0,8,16,24}+r cover all).
// ---------------------------------------------------------------------------
#define PROJ_LDS 130

__global__ __launch_bounds__(256)
void proj_kernel(const float* __restrict__ x,
                 const float* __restrict__ Wq, const float* __restrict__ bq,
                 const float* __restrict__ Wk, const float* __restrict__ bk,
                 const float* __restrict__ Wv, const float* __restrict__ bv)
{
    const float* W; const float* bias; float* out;
    if (blockIdx.z == 0)      { W = Wq; bias = bq; out = g_Q; }
    else if (blockIdx.z == 1) { W = Wk; bias = bk; out = g_K; }
    else                      { W = Wv; bias = bv; out = g_V; }

    __shared__ float xs[16][PROJ_LDS];   // xs[k][row]
    __shared__ float ws[16][PROJ_LDS];   // ws[k][col]

    const int tid = threadIdx.x;          // 0..255
    const int tx  = tid & 15;             // 16 col groups
    const int ty  = tid >> 4;             // 16 row groups
    const int rowBase = blockIdx.x * 128;

    float acc[8][8];
    #pragma unroll
    for (int i = 0; i < 8; i++)
        #pragma unroll
        for (int j = 0; j < 8; j++) acc[i][j] = 0.f;

    for (int k0 = 0; k0 < DM; k0 += 16) {
        // Load 128x16 tiles of x and W, stored k-major in smem.
        // 2048 floats each = 512 float4 = 2 float4 per thread.
        #pragma unroll
        for (int l = 0; l < 2; l++) {
            int idx = tid + l * 256;          // 0..511
            int r   = idx >> 2;               // 0..127
            int kq  = (idx & 3) * 4;          // 0,4,8,12
            float4 v = *(const float4*)&x[(size_t)(rowBase + r) * DM + k0 + kq];
            xs[kq + 0][r] = v.x; xs[kq + 1][r] = v.y;
            xs[kq + 2][r] = v.z; xs[kq + 3][r] = v.w;
            float4 w = *(const float4*)&W[(size_t)r * DM + k0 + kq];
            ws[kq + 0][r] = w.x; ws[kq + 1][r] = w.y;
            ws[kq + 2][r] = w.z; ws[kq + 3][r] = w.w;
        }
        __syncthreads();

        #pragma unroll
        for (int kk = 0; kk < 16; kk++) {
            float a[8], b[8];
            #pragma unroll
            for (int i = 0; i < 8; i++) a[i] = xs[kk][ty * 8 + i];     // broadcast
            #pragma unroll
            for (int j = 0; j < 8; j++) b[j] = ws[kk][tx + 16 * j];    // conflict-free
            #pragma unroll
            for (int i = 0; i < 8; i++)
                #pragma unroll
                for (int j = 0; j < 8; j++)
                    acc[i][j] += a[i] * b[j];
        }
        __syncthreads();
    }

    #pragma unroll
    for (int i = 0; i < 8; i++) {
        int r = rowBase + ty * 8 + i;
        #pragma unroll
        for (int j = 0; j < 8; j++) {
            int c = tx + 16 * j;
            out[(size_t)r * DK + c] = acc[i][j] + bias[c];
        }
    }
}

// ---------------------------------------------------------------------------
// Kernel 2: flash attention, fp32.
//   out = softmax((Q K^T)/sqrt(DK)) @ V
// BQ = 64 Q rows per block, BKV = 64 K/V rows per iteration, 256 threads.
// Thread grid 16x16:
//   S tile   : thread owns rows ty*4+i (i<4), cols tx+16*j (j<4)
//   O accum  : thread owns rows ty*4+i, cols tx*8+d (d<8)  (float4-friendly)
// Row softmax reductions via shfl_xor over the 16-lane tx group.
// Dynamic smem: Qs/Ks/Vs [64][132] + Ps [64][68]  = 118784 bytes.
// ---------------------------------------------------------------------------
#define FA_LDS 132    // 128 + 4, keeps 16B alignment, breaks 512B-stride conflicts
#define PS_LDS 68
#define FA_SMEM_BYTES ((3 * 64 * FA_LDS + 64 * PS_LDS) * 4)

__global__ __launch_bounds__(256)
void flash_kernel(float* __restrict__ out)
{
    extern __shared__ float smem[];
    float* Qs = smem;                      // 64*132
    float* Ks = Qs + 64 * FA_LDS;          // 64*132
    float* Vs = Ks + 64 * FA_LDS;          // 64*132
    float* Ps = Vs + 64 * FA_LDS;          // 64*68

    const int tid = threadIdx.x;
    const int tx  = tid & 15;
    const int ty  = tid >> 4;
    const int qBase = blockIdx.x * 64;
    const float rscale = 0.088388347648318447f;   // 1/sqrt(128)

    // Load Q tile (64x128) once: 2048 float4, 8 per thread.
    #pragma unroll
    for (int l = 0; l < 8; l++) {
        int idx = tid + l * 256;
        int r   = idx >> 5;              // 0..63
        int kq  = (idx & 31) * 4;        // 0..124
        *(float4*)&Qs[r * FA_LDS + kq] =
            *(const float4*)&g_Q[(size_t)(qBase + r) * DK + kq];
    }

    float m[4], lsum[4], o[4][8];
    #pragma unroll
    for (int i = 0; i < 4; i++) {
        m[i] = -INFINITY; lsum[i] = 0.f;
        #pragma unroll
        for (int d = 0; d < 8; d++) o[i][d] = 0.f;
    }

    for (int kv0 = 0; kv0 < SEQ; kv0 += 64) {
        __syncthreads();   // prev PV done reading Vs/Ps before overwrite
        #pragma unroll
        for (int l = 0; l < 8; l++) {
            int idx = tid + l * 256;
            int r   = idx >> 5;
            int kq  = (idx & 31) * 4;
            *(float4*)&Ks[r * FA_LDS + kq] =
                *(const float4*)&g_K[(size_t)(kv0 + r) * DK + kq];
            *(float4*)&Vs[r * FA_LDS + kq] =
                *(const float4*)&g_V[(size_t)(kv0 + r) * DK + kq];
        }
        __syncthreads();

        // ---- S = Q K^T (4x4 per thread), float4 over the k dimension ----
        float s[4][4];
        #pragma unroll
        for (int i = 0; i < 4; i++)
            #pragma unroll
            for (int j = 0; j < 4; j++) s[i][j] = 0.f;

        for (int k0 = 0; k0 < DK; k0 += 4) {
            float4 a[4], b[4];
            #pragma unroll
            for (int i = 0; i < 4; i++)
                a[i] = *(const float4*)&Qs[(ty * 4 + i) * FA_LDS + k0];
            #pragma unroll
            for (int j = 0; j < 4; j++)
                b[j] = *(const float4*)&Ks[(tx + 16 * j) * FA_LDS + k0];
            #pragma unroll
            for (int i = 0; i < 4; i++)
                #pragma unroll
                for (int j = 0; j < 4; j++)
                    s[i][j] += a[i].x * b[j].x + a[i].y * b[j].y
                             + a[i].z * b[j].z + a[i].w * b[j].w;
        }

        // ---- online softmax per Q row ----
        #pragma unroll
        for (int i = 0; i < 4; i++) {
            float tm = -INFINITY;
            #pragma unroll
            for (int j = 0; j < 4; j++) {
                s[i][j] *= rscale;
                tm = fmaxf(tm, s[i][j]);
            }
            #pragma unroll
            for (int off = 8; off >= 1; off >>= 1)
                tm = fmaxf(tm, __shfl_xor_sync(0xffffffffu, tm, off));
            float mn    = fmaxf(m[i], tm);
            float alpha = __expf(m[i] - mn);
            float rs = 0.f;
            #pragma unroll
            for (int j = 0; j < 4; j++) {
                s[i][j] = __expf(s[i][j] - mn);
                rs += s[i][j];
            }
            #pragma unroll
            for (int off = 8; off >= 1; off >>= 1)
                rs += __shfl_xor_sync(0xffffffffu, rs, off);
            lsum[i] = lsum[i] * alpha + rs;
            m[i] = mn;
            #pragma unroll
            for (int d = 0; d < 8; d++) o[i][d] *= alpha;
            #pragma unroll
            for (int j = 0; j < 4; j++)
                Ps[(ty * 4 + i) * PS_LDS + tx + 16 * j] = s[i][j];
        }
        __syncthreads();

        // ---- O += P @ V ----
        #pragma unroll 2
        for (int k = 0; k < 64; k++) {
            float4 v0 = *(const float4*)&Vs[k * FA_LDS + tx * 8];
            float4 v1 = *(const float4*)&Vs[k * FA_LDS + tx * 8 + 4];
            float a[4];
            #pragma unroll
            for (int i = 0; i < 4; i++) a[i] = Ps[(ty * 4 + i) * PS_LDS + k];
            #pragma unroll
            for (int i = 0; i < 4; i++) {
                o[i][0] += a[i] * v0.x; o[i][1] += a[i] * v0.y;
                o[i][2] += a[i] * v0.z; o[i][3] += a[i] * v0.w;
                o[i][4] += a[i] * v1.x; o[i][5] += a[i] * v1.y;
                o[i][6] += a[i] * v1.z; o[i][7] += a[i] * v1.w;
            }
        }
    }

    // ---- epilogue ----
    #pragma unroll
    for (int i = 0; i < 4; i++) {
        float inv = 1.f / lsum[i];
        int row = qBase + ty * 4 + i;
        float4 r0 = make_float4(o[i][0] * inv, o[i][1] * inv,
                                o[i][2] * inv, o[i][3] * inv);
        float4 r1 = make_float4(o[i][4] * inv, o[i][5] * inv,
                                o[i][6] * inv, o[i][7] * inv);
        *(float4*)&out[(size_t)row * DK + tx * 8]     = r0;
        *(float4*)&out[(size_t)row * DK + tx * 8 + 4] = r1;
    }
}

// ---------------------------------------------------------------------------
extern "C" void kernel_launch(void* const* d_in, const int* in_sizes, int n_in,
                              void* d_out, int out_size)
{
    (void)in_sizes; (void)n_in; (void)out_size;
    const float* x  = (const float*)d_in[0];
    const float* Wq = (const float*)d_in[1];
    const float* bq = (const float*)d_in[2];
    const float* Wk = (const float*)d_in[3];
    const float* bk = (const float*)d_in[4];
    const float* Wv = (const float*)d_in[5];
    const float* bv = (const float*)d_in[6];
    float* out = (float*)d_out;

    cudaFuncSetAttribute(flash_kernel,
                         cudaFuncAttributeMaxDynamicSharedMemorySize,
                         FA_SMEM_BYTES);

    dim3 gProj(SEQ / 128, 1, 3);
    proj_kernel<<<gProj, 256>>>(x, Wq, bq, Wk, bk, Wv, bv);

    flash_kernel<<<SEQ / 64, 256, FA_SMEM_BYTES>>>(out);
}